// round 9
// baseline (speedup 1.0000x reference)
#include <cuda_runtime.h>
#include <cuda_bf16.h>
#include <cstdint>

#define N_NODES 50000
#define N_EDGES 800000
#define IN_DIM  256
#define HID     128
#define CAP     96          // per-node bucket capacity (Poisson(16) -> P(>=96) ~ 1e-40)

// -------- scratch (device globals; no allocations allowed) ------------------
__device__ float g_fts [N_NODES * HID];      // gemm1 out (read-only during seg1 phase)
__device__ float g_z   [N_NODES * HID];      // seg1 out / gemm2 in
__device__ float g_fts2[N_NODES * HID];      // gemm2 out / seg2 in
__device__ int   g_cnt[N_NODES];             // per-node edge count
__device__ int2  g_epack[N_NODES * CAP];     // (src, weight-bits) buckets

// -------- streams/events (host-side only; no device memory) -----------------
static cudaStream_t g_s2;
static cudaEvent_t  g_ev_fork, g_ev_csr, g_ev_sh0, g_ev_g2h0;
static struct StreamInit {
    StreamInit() {
        cudaStreamCreateWithFlags(&g_s2, cudaStreamNonBlocking);
        cudaEventCreateWithFlags(&g_ev_fork, cudaEventDisableTiming);
        cudaEventCreateWithFlags(&g_ev_csr,  cudaEventDisableTiming);
        cudaEventCreateWithFlags(&g_ev_sh0,  cudaEventDisableTiming);
        cudaEventCreateWithFlags(&g_ev_g2h0, cudaEventDisableTiming);
    }
} g_stream_init;

__device__ __forceinline__ uint32_t f2tf32(float f) {
    uint32_t r;
    asm("cvt.rna.tf32.f32 %0, %1;" : "=r"(r) : "f"(f));
    return r;
}

__device__ __forceinline__ void mma_tf32(float* d, const uint32_t* a, const uint32_t* b) {
    asm volatile(
        "mma.sync.aligned.m16n8k8.row.col.f32.tf32.tf32.f32 "
        "{%0,%1,%2,%3}, {%4,%5,%6,%7}, {%8,%9}, {%0,%1,%2,%3};"
        : "+f"(d[0]), "+f"(d[1]), "+f"(d[2]), "+f"(d[3])
        : "r"(a[0]), "r"(a[1]), "r"(a[2]), "r"(a[3]), "r"(b[0]), "r"(b[1]));
}

// ===========================================================================
// bucket build: zero counts -> scatter into buckets -> pad to multiple of 8
// ===========================================================================
__global__ void zero_int_kernel(int* __restrict__ p, int n) {
    int i = blockIdx.x * blockDim.x + threadIdx.x;
    if (i < n) p[i] = 0;
}

__global__ void fill_kernel(const int* __restrict__ ei, const float* __restrict__ ew,
                            int* __restrict__ cnt, int2* __restrict__ epack)
{
    int i = blockIdx.x * blockDim.x + threadIdx.x;
    if (i >= N_EDGES) return;
    int src   = __ldg(&ei[i]);
    int dst   = __ldg(&ei[N_EDGES + i]);
    int wbits = __float_as_int(__ldg(&ew[i]));
    int pos = atomicAdd(&cnt[dst], 1);
    if (pos < CAP)                                  // never triggers; OOB guard
        epack[(size_t)dst * CAP + pos] = make_int2(src, wbits);
}

// pad bucket [cnt, roundup8(cnt)) with (src=0, w=0): 0*v contributes exactly 0
__global__ void pad_kernel(const int* __restrict__ cnt, int2* __restrict__ epack) {
    int node = blockIdx.x * blockDim.x + threadIdx.x;
    if (node >= N_NODES) return;
    int c  = min(cnt[node], CAP);
    int c8 = min((c + 7) & ~7, CAP);
    int2* ep = epack + (size_t)node * CAP;
    for (int i = c; i < c8; i++) ep[i] = make_int2(0, 0);
}

// ===========================================================================
// tf32 mma.sync GEMM: C[M][128] = A[M][K] @ W[128][K]^T
// CTA = 128x128 tile, 256 threads (8 warps), warp = 32x64 via m16n8k8.
// ===========================================================================
#define SSTRIDE 36

template <int K>
__global__ __launch_bounds__(256) void gemm_mma_kernel(
    const float* __restrict__ A, const float* __restrict__ W,
    float* __restrict__ C, int M)
{
    constexpr int NC = K / 32;
    __shared__ uint32_t As[128 * SSTRIDE];
    __shared__ uint32_t Ws[128 * SSTRIDE];

    const int tid  = threadIdx.x;
    const int lane = tid & 31;
    const int w    = tid >> 5;
    const int m0   = blockIdx.x * 128;
    const int wr   = (w & 3) * 32;
    const int wc   = (w >> 2) * 64;
    const int grp  = lane >> 2;
    const int tig  = lane & 3;

    float acc[2][8][4];
#pragma unroll
    for (int mt = 0; mt < 2; mt++)
#pragma unroll
        for (int nt = 0; nt < 8; nt++)
#pragma unroll
            for (int j = 0; j < 4; j++) acc[mt][nt][j] = 0.f;

    float4 pa[4], pw[4];
#pragma unroll
    for (int t = 0; t < 4; t++) {
        int idx = tid + t * 256;
        int r = idx >> 3, c4 = idx & 7;
        int m = m0 + r;
        pa[t] = (m < M) ? *reinterpret_cast<const float4*>(&A[(size_t)m * K + c4 * 4])
                        : make_float4(0.f, 0.f, 0.f, 0.f);
        pw[t] = *reinterpret_cast<const float4*>(&W[(size_t)r * K + c4 * 4]);
    }

#pragma unroll 1
    for (int ch = 0; ch < NC; ch++) {
        if (ch) __syncthreads();
#pragma unroll
        for (int t = 0; t < 4; t++) {
            int idx = tid + t * 256;
            int r = idx >> 3, c4 = idx & 7;
            uint32_t* ap = &As[r * SSTRIDE + c4 * 4];
            ap[0] = f2tf32(pa[t].x); ap[1] = f2tf32(pa[t].y);
            ap[2] = f2tf32(pa[t].z); ap[3] = f2tf32(pa[t].w);
            uint32_t* wp = &Ws[r * SSTRIDE + c4 * 4];
            wp[0] = f2tf32(pw[t].x); wp[1] = f2tf32(pw[t].y);
            wp[2] = f2tf32(pw[t].z); wp[3] = f2tf32(pw[t].w);
        }
        __syncthreads();

        if (ch + 1 < NC) {
#pragma unroll
            for (int t = 0; t < 4; t++) {
                int idx = tid + t * 256;
                int r = idx >> 3, c4 = idx & 7;
                int m = m0 + r;
                int ko = (ch + 1) * 32 + c4 * 4;
                pa[t] = (m < M) ? *reinterpret_cast<const float4*>(&A[(size_t)m * K + ko])
                                : make_float4(0.f, 0.f, 0.f, 0.f);
                pw[t] = *reinterpret_cast<const float4*>(&W[(size_t)r * K + ko]);
            }
        }

#pragma unroll
        for (int kk = 0; kk < 4; kk++) {
            uint32_t af[2][4], bf[8][2];
#pragma unroll
            for (int mt = 0; mt < 2; mt++) {
                int rb = wr + mt * 16;
                af[mt][0] = As[(rb + grp)     * SSTRIDE + kk * 8 + tig];
                af[mt][1] = As[(rb + grp + 8) * SSTRIDE + kk * 8 + tig];
                af[mt][2] = As[(rb + grp)     * SSTRIDE + kk * 8 + tig + 4];
                af[mt][3] = As[(rb + grp + 8) * SSTRIDE + kk * 8 + tig + 4];
            }
#pragma unroll
            for (int nt = 0; nt < 8; nt++) {
                int nb = wc + nt * 8 + grp;
                bf[nt][0] = Ws[nb * SSTRIDE + kk * 8 + tig];
                bf[nt][1] = Ws[nb * SSTRIDE + kk * 8 + tig + 4];
            }
#pragma unroll
            for (int mt = 0; mt < 2; mt++)
#pragma unroll
                for (int nt = 0; nt < 8; nt++)
                    mma_tf32(acc[mt][nt], af[mt], bf[nt]);
        }
    }

#pragma unroll
    for (int mt = 0; mt < 2; mt++) {
        int r0 = m0 + wr + mt * 16 + grp;
        int r1 = r0 + 8;
#pragma unroll
        for (int nt = 0; nt < 8; nt++) {
            int col = wc + nt * 8 + tig * 2;
            if (r0 < M)
                *reinterpret_cast<float2*>(&C[(size_t)r0 * 128 + col]) =
                    make_float2(acc[mt][nt][0], acc[mt][nt][1]);
            if (r1 < M)
                *reinterpret_cast<float2*>(&C[(size_t)r1 * 128 + col]) =
                    make_float2(acc[mt][nt][2], acc[mt][nt][3]);
        }
    }
}

// ===========================================================================
// Fused segmented gather-sum + bias + PReLU (one warp per dst node).
// Buckets padded to multiples of 8 -> pure 8-unrolled loop, 8 LDG.128 in
// flight per warp, no remainder. Descriptors broadcast via shfl.
// ===========================================================================
__global__ __launch_bounds__(256) void seg_kernel(
    const float* __restrict__ fts,
    const int*   __restrict__ cnt,
    const int2*  __restrict__ epack,
    const float* __restrict__ b,
    const float* __restrict__ a,
    float*       __restrict__ out,
    int node_base, int n_nodes)
{
    int widx = (blockIdx.x * blockDim.x + threadIdx.x) >> 5;
    int lane = threadIdx.x & 31;
    if (widx >= n_nodes) return;
    const int node = node_base + widx;

    const int deg8 = min((cnt[node] + 7) & ~7, CAP);   // padded length
    const int2* ep = epack + (size_t)node * CAP;

    float4 acc = make_float4(0.f, 0.f, 0.f, 0.f);

#pragma unroll 1
    for (int c0 = 0; c0 < deg8; c0 += 32) {
        const int n = min(deg8 - c0, 32);              // multiple of 8
        int2 ed = (lane < n) ? __ldg(&ep[c0 + lane]) : make_int2(0, 0);

#pragma unroll 1
        for (int e = 0; e < n; e += 8) {
            int s[8]; float wgt[8];
#pragma unroll
            for (int j = 0; j < 8; j++) {
                s[j]   = __shfl_sync(0xFFFFFFFFu, ed.x, e + j);
                wgt[j] = __int_as_float(__shfl_sync(0xFFFFFFFFu, ed.y, e + j));
            }
            float4 v[8];
#pragma unroll
            for (int j = 0; j < 8; j++)
                v[j] = reinterpret_cast<const float4*>(fts + (size_t)s[j] * HID)[lane];
#pragma unroll
            for (int j = 0; j < 8; j++) {
                acc.x += wgt[j] * v[j].x;
                acc.y += wgt[j] * v[j].y;
                acc.z += wgt[j] * v[j].z;
                acc.w += wgt[j] * v[j].w;
            }
        }
    }

    float alpha = a[0];
    float4 bb = reinterpret_cast<const float4*>(b)[lane];
    acc.x += bb.x; acc.y += bb.y; acc.z += bb.z; acc.w += bb.w;
    acc.x = acc.x >= 0.f ? acc.x : alpha * acc.x;
    acc.y = acc.y >= 0.f ? acc.y : alpha * acc.y;
    acc.z = acc.z >= 0.f ? acc.z : alpha * acc.z;
    acc.w = acc.w >= 0.f ? acc.w : alpha * acc.w;

    reinterpret_cast<float4*>(out + (size_t)node * HID)[lane] = acc;
}

// ===========================================================================
extern "C" void kernel_launch(void* const* d_in, const int* in_sizes, int n_in,
                              void* d_out, int out_size)
{
    const float* x  = (const float*)d_in[0];
    const int*   ei = (const int*)  d_in[1];
    const float* ew = (const float*)d_in[2];
    const float* W1 = (const float*)d_in[3];
    const float* b1 = (const float*)d_in[4];
    const float* a1 = (const float*)d_in[5];
    const float* W2 = (const float*)d_in[6];
    const float* b2 = (const float*)d_in[7];
    const float* a2 = (const float*)d_in[8];
    float* out = (float*)d_out;

    float *fts, *z, *fts2;
    int *cnt;
    int2 *epack;
    cudaGetSymbolAddress((void**)&fts,   g_fts);
    cudaGetSymbolAddress((void**)&z,     g_z);
    cudaGetSymbolAddress((void**)&fts2,  g_fts2);
    cudaGetSymbolAddress((void**)&cnt,   g_cnt);
    cudaGetSymbolAddress((void**)&epack, g_epack);

    const int EB  = (N_EDGES + 255) / 256;
    const int NBK = (N_NODES + 255) / 256;
    const int GB  = (N_NODES + 127) / 128;             // 391 tiles

    // node halves for the seg1/gemm2 pipeline
    const int H0_TILES = 196, H0 = H0_TILES * 128;     // 25088 nodes
    const int H1 = N_NODES - H0;                       // 24912 nodes
    const int H1_TILES = GB - H0_TILES;                // 195
    const int SGB0 = (H0 * 32 + 255) / 256;
    const int SGB1 = (H1 * 32 + 255) / 256;
    const int SGBF = (N_NODES * 32 + 255) / 256;

    // ---- fork: bucket build on g_s2, concurrent with gemm1 on stream 0 ----
    cudaEventRecord(g_ev_fork, 0);
    cudaStreamWaitEvent(g_s2, g_ev_fork, 0);

    zero_int_kernel<<<NBK, 256, 0, g_s2>>>(cnt, N_NODES);
    fill_kernel<<<EB, 256, 0, g_s2>>>(ei, ew, cnt, epack);
    pad_kernel<<<NBK, 256, 0, g_s2>>>(cnt, epack);
    cudaEventRecord(g_ev_csr, g_s2);

    gemm_mma_kernel<IN_DIM><<<GB, 256>>>(x, W1, fts, N_NODES);

    // ---- join: seg1 needs buckets + gemm1 ----
    cudaStreamWaitEvent(0, g_ev_csr, 0);

    // seg1 half0 -> z[0:H0]; then gemm2 half0 (z->fts2) on s2 concurrently
    // with seg1 half1 (reads fts ONLY; fts2 disjoint -> race-free).
    seg_kernel<<<SGB0, 256>>>(fts, cnt, epack, b1, a1, z, 0, H0);
    cudaEventRecord(g_ev_sh0, 0);
    cudaStreamWaitEvent(g_s2, g_ev_sh0, 0);
    gemm_mma_kernel<HID><<<H0_TILES, 256, 0, g_s2>>>(z, W2, fts2, H0);
    cudaEventRecord(g_ev_g2h0, g_s2);

    seg_kernel<<<SGB1, 256>>>(fts, cnt, epack, b1, a1, z, H0, H1);
    gemm_mma_kernel<HID><<<H1_TILES, 256>>>(z + (size_t)H0 * HID, W2,
                                            fts2 + (size_t)H0 * HID, H1);

    // seg2 needs both gemm2 halves
    cudaStreamWaitEvent(0, g_ev_g2h0, 0);
    seg_kernel<<<SGBF, 256>>>(fts2, cnt, epack, b2, a2, out, 0, N_NODES);
}